// round 5
// baseline (speedup 1.0000x reference)
#include <cuda_runtime.h>
#include <math.h>

// Problem constants
#define BATCH 64
#define NSEQ  512
#define HDIM  768
#define M_TOTAL (BATCH * NSEQ)   // 32768

// Scratch for xW = X @ W  (96 MB, __device__ global — no allocations)
__device__ float g_xw[(size_t)M_TOTAL * HDIM];

// ---------------------------------------------------------------------------
// Kernel A: g_xw[m, k] = sum_h X[m, h] * W[h, k]
// M=32768, N=768, K=768. 128x128 block tile, K-step 8, 256 threads, 8x8 microtile.
// ---------------------------------------------------------------------------
__global__ __launch_bounds__(256) void gemm_xw_kernel(const float* __restrict__ X,
                                                      const float* __restrict__ W) {
    __shared__ float As[8][128];   // [k][m]
    __shared__ float Bs[8][128];   // [k][n]

    const int tid = threadIdx.x;
    const int bm = blockIdx.y * 128;
    const int bn = blockIdx.x * 128;
    const int tr = (tid / 16) * 8;   // row offset in tile
    const int tc = (tid % 16) * 8;   // col offset in tile

    float acc[8][8];
#pragma unroll
    for (int i = 0; i < 8; i++)
#pragma unroll
        for (int j = 0; j < 8; j++) acc[i][j] = 0.0f;

    const int a_row = tid >> 1;          // 0..127
    const int a_k4  = (tid & 1) * 4;     // 0 or 4
    const int b_k   = tid >> 5;          // 0..7
    const int b_col = (tid & 31) * 4;    // 0..124

    const float* Aptr = X + (size_t)(bm + a_row) * HDIM + a_k4;
    const float* Bptr = W + (size_t)b_k * HDIM + bn + b_col;

    for (int k0 = 0; k0 < HDIM; k0 += 8) {
        float4 av = *(const float4*)(Aptr + k0);
        float4 bv = *(const float4*)(Bptr + (size_t)k0 * HDIM);

        __syncthreads();
        As[a_k4 + 0][a_row] = av.x;
        As[a_k4 + 1][a_row] = av.y;
        As[a_k4 + 2][a_row] = av.z;
        As[a_k4 + 3][a_row] = av.w;
        *(float4*)&Bs[b_k][b_col] = bv;
        __syncthreads();

#pragma unroll
        for (int k = 0; k < 8; k++) {
            float a[8], b[8];
            *(float4*)(a)     = *(const float4*)&As[k][tr];
            *(float4*)(a + 4) = *(const float4*)&As[k][tr + 4];
            *(float4*)(b)     = *(const float4*)&Bs[k][tc];
            *(float4*)(b + 4) = *(const float4*)&Bs[k][tc + 4];
#pragma unroll
            for (int i = 0; i < 8; i++)
#pragma unroll
                for (int j = 0; j < 8; j++)
                    acc[i][j] = fmaf(a[i], b[j], acc[i][j]);
        }
    }

    float* out = g_xw + (size_t)(bm + tr) * HDIM + bn + tc;
#pragma unroll
    for (int i = 0; i < 8; i++) {
        *(float4*)(out + (size_t)i * HDIM)     = make_float4(acc[i][0], acc[i][1], acc[i][2], acc[i][3]);
        *(float4*)(out + (size_t)i * HDIM + 4) = make_float4(acc[i][4], acc[i][5], acc[i][6], acc[i][7]);
    }
}

// ---------------------------------------------------------------------------
// Kernel B: fused scores + softmax + output per (batch, 64-row tile).
//   S[i,j] = xW[b,i,:] . X[b,j,:] + bias  (j != i), 0 on diagonal
//   P = softmax_row(S);  out[b,i,:] = sum_j P[i,j] X[b,j,:]
// Dynamic smem: S[64][516] + Axw[16][68] + Bt[16][132]
// ---------------------------------------------------------------------------
#define SPAD 516
#define APAD 68
#define BPAD 132
#define SMEM_FLOATS (64 * SPAD + 16 * APAD + 16 * BPAD)

__global__ __launch_bounds__(256) void attn_kernel(const float* __restrict__ X,
                                                   const float* __restrict__ bias_ptr,
                                                   float* __restrict__ out) {
    extern __shared__ float sm[];
    float* S   = sm;                    // 64 x SPAD
    float* Axw = sm + 64 * SPAD;        // 16 x APAD   (k-major xW tile)
    float* Bt  = Axw + 16 * APAD;       // 16 x BPAD   (k-major X tile)

    const int tid = threadIdx.x;
    const int b  = blockIdx.y;
    const int i0 = blockIdx.x * 64;
    const float bias = bias_ptr[0];

    const float* Xb  = X + (size_t)b * NSEQ * HDIM;
    const float* XWb = g_xw + (size_t)(b * NSEQ + i0) * HDIM;

    const int tr = (tid / 16) * 4;    // 0..60  (row microtile)
    const int tc = (tid % 16) * 8;    // 0..120 (col microtile)

    // staging indices (score phase)
    const int ar = tid >> 2;           // 0..63
    const int ak = (tid & 3) * 4;      // 0,4,8,12
    const int bj = tid >> 1;           // 0..127
    const int bk = (tid & 1) * 8;      // 0,8

    // ---------------- score GEMM: S = xW_tile @ Xb^T + bias, diag=0 ----------
    for (int jt = 0; jt < 4; jt++) {
        const int j0 = jt * 128;
        float acc[4][8];
#pragma unroll
        for (int u = 0; u < 4; u++)
#pragma unroll
            for (int v = 0; v < 8; v++) acc[u][v] = 0.0f;

        for (int kk = 0; kk < HDIM; kk += 16) {
            float4 av  = *(const float4*)(XWb + (size_t)ar * HDIM + kk + ak);
            const float* xrow = Xb + (size_t)(j0 + bj) * HDIM + kk + bk;
            float4 bv0 = *(const float4*)(xrow);
            float4 bv1 = *(const float4*)(xrow + 4);

            __syncthreads();
            Axw[(ak + 0) * APAD + ar] = av.x;
            Axw[(ak + 1) * APAD + ar] = av.y;
            Axw[(ak + 2) * APAD + ar] = av.z;
            Axw[(ak + 3) * APAD + ar] = av.w;
            Bt[(bk + 0) * BPAD + bj] = bv0.x;
            Bt[(bk + 1) * BPAD + bj] = bv0.y;
            Bt[(bk + 2) * BPAD + bj] = bv0.z;
            Bt[(bk + 3) * BPAD + bj] = bv0.w;
            Bt[(bk + 4) * BPAD + bj] = bv1.x;
            Bt[(bk + 5) * BPAD + bj] = bv1.y;
            Bt[(bk + 6) * BPAD + bj] = bv1.z;
            Bt[(bk + 7) * BPAD + bj] = bv1.w;
            __syncthreads();

#pragma unroll
            for (int k = 0; k < 16; k++) {
                float a[4], bb[8];
                *(float4*)(a)      = *(const float4*)&Axw[k * APAD + tr];
                *(float4*)(bb)     = *(const float4*)&Bt[k * BPAD + tc];
                *(float4*)(bb + 4) = *(const float4*)&Bt[k * BPAD + tc + 4];
#pragma unroll
                for (int u = 0; u < 4; u++)
#pragma unroll
                    for (int v = 0; v < 8; v++)
                        acc[u][v] = fmaf(a[u], bb[v], acc[u][v]);
            }
        }

        // store scores (bias everywhere except diagonal, which is 0)
#pragma unroll
        for (int u = 0; u < 4; u++)
#pragma unroll
            for (int v = 0; v < 8; v++) {
                const int ig = i0 + tr + u;
                const int jg = j0 + tc + v;
                S[(tr + u) * SPAD + jg] = (ig == jg) ? 0.0f : (acc[u][v] + bias);
            }
    }
    __syncthreads();

    // ---------------- softmax: one warp per row, 8 rows per warp ------------
    const int warp = tid >> 5;
    const int lane = tid & 31;
    for (int rr = 0; rr < 8; rr++) {
        const int row = warp * 8 + rr;
        float* Srow = S + row * SPAD;
        float m = -1e30f;
        for (int j = lane; j < NSEQ; j += 32) m = fmaxf(m, Srow[j]);
#pragma unroll
        for (int o = 16; o > 0; o >>= 1) m = fmaxf(m, __shfl_xor_sync(0xffffffffu, m, o));
        float s = 0.0f;
        for (int j = lane; j < NSEQ; j += 32) {
            float e = __expf(Srow[j] - m);
            Srow[j] = e;
            s += e;
        }
#pragma unroll
        for (int o = 16; o > 0; o >>= 1) s += __shfl_xor_sync(0xffffffffu, s, o);
        const float inv = 1.0f / s;
        for (int j = lane; j < NSEQ; j += 32) Srow[j] *= inv;
    }
    __syncthreads();

    // ---------------- output GEMM: O = P @ Xb  (64 x 768, K = 512) ----------
    const int ok = tid >> 4;           // 0..15 (k-row of staged tile)
    const int oc = (tid & 15) * 8;     // 0..120

    for (int ht = 0; ht < 6; ht++) {
        const int h0 = ht * 128;
        float acc[4][8];
#pragma unroll
        for (int u = 0; u < 4; u++)
#pragma unroll
            for (int v = 0; v < 8; v++) acc[u][v] = 0.0f;

        for (int kk = 0; kk < NSEQ; kk += 16) {
            const float* xrow = Xb + (size_t)(kk + ok) * HDIM + h0 + oc;
            float4 v0 = *(const float4*)(xrow);
            float4 v1 = *(const float4*)(xrow + 4);

            __syncthreads();
            *(float4*)&Bt[ok * BPAD + oc]     = v0;
            *(float4*)&Bt[ok * BPAD + oc + 4] = v1;
            __syncthreads();

#pragma unroll
            for (int k = 0; k < 16; k++) {
                float bb[8];
                *(float4*)(bb)     = *(const float4*)&Bt[k * BPAD + tc];
                *(float4*)(bb + 4) = *(const float4*)&Bt[k * BPAD + tc + 4];
#pragma unroll
                for (int u = 0; u < 4; u++) {
                    const float a = S[(tr + u) * SPAD + kk + k];
#pragma unroll
                    for (int v = 0; v < 8; v++)
                        acc[u][v] = fmaf(a, bb[v], acc[u][v]);
                }
            }
        }

        float* O = out + (size_t)(b * NSEQ + i0 + tr) * HDIM + h0 + tc;
#pragma unroll
        for (int u = 0; u < 4; u++) {
            *(float4*)(O + (size_t)u * HDIM)     = make_float4(acc[u][0], acc[u][1], acc[u][2], acc[u][3]);
            *(float4*)(O + (size_t)u * HDIM + 4) = make_float4(acc[u][4], acc[u][5], acc[u][6], acc[u][7]);
        }
    }
}

// ---------------------------------------------------------------------------
extern "C" void kernel_launch(void* const* d_in, const int* in_sizes, int n_in,
                              void* d_out, int out_size) {
    const float* X    = (const float*)d_in[0];   // [64, 512, 768]
    const float* W    = (const float*)d_in[1];   // [768, 768]
    const float* bptr = (const float*)d_in[2];   // [1]
    float* out = (float*)d_out;                  // [64, 512, 768]

    (void)in_sizes; (void)n_in; (void)out_size;

    const size_t smem_bytes = (size_t)SMEM_FLOATS * sizeof(float);  // ~141.5 KB
    cudaFuncSetAttribute(attn_kernel, cudaFuncAttributeMaxDynamicSharedMemorySize,
                         (int)smem_bytes);

    // Kernel A: xW = X @ W
    dim3 gridA(HDIM / 128, M_TOTAL / 128);   // (6, 256)
    gemm_xw_kernel<<<gridA, 256>>>(X, W);

    // Kernel B: fused scores + softmax + output
    dim3 gridB(NSEQ / 64, BATCH);            // (8, 64)
    attn_kernel<<<gridB, 256, smem_bytes>>>(X, bptr, out);
}

// round 6
// speedup vs baseline: 1.0010x; 1.0010x over previous
#include <cuda_runtime.h>
#include <math.h>

// Problem constants
#define BATCH 64
#define NSEQ  512
#define HDIM  768
#define M_TOTAL (BATCH * NSEQ)   // 32768

// Scratch for xW = X @ W  (96 MB, __device__ global — no allocations)
__device__ float g_xw[(size_t)M_TOTAL * HDIM];

// ---------------------------------------------------------------------------
// Kernel A: g_xw[m, k] = sum_h X[m, h] * W[h, k]
// M=32768, N=768, K=768. 128x128 block tile, K-step 8, 256 threads, 8x8 microtile.
// ---------------------------------------------------------------------------
__global__ __launch_bounds__(256) void gemm_xw_kernel(const float* __restrict__ X,
                                                      const float* __restrict__ W) {
    __shared__ float As[8][128];   // [k][m]
    __shared__ float Bs[8][128];   // [k][n]

    const int tid = threadIdx.x;
    const int bm = blockIdx.y * 128;
    const int bn = blockIdx.x * 128;
    const int tr = (tid / 16) * 8;   // row offset in tile
    const int tc = (tid % 16) * 8;   // col offset in tile

    float acc[8][8];
#pragma unroll
    for (int i = 0; i < 8; i++)
#pragma unroll
        for (int j = 0; j < 8; j++) acc[i][j] = 0.0f;

    const int a_row = tid >> 1;          // 0..127
    const int a_k4  = (tid & 1) * 4;     // 0 or 4
    const int b_k   = tid >> 5;          // 0..7
    const int b_col = (tid & 31) * 4;    // 0..124

    const float* Aptr = X + (size_t)(bm + a_row) * HDIM + a_k4;
    const float* Bptr = W + (size_t)b_k * HDIM + bn + b_col;

    for (int k0 = 0; k0 < HDIM; k0 += 8) {
        float4 av = *(const float4*)(Aptr + k0);
        float4 bv = *(const float4*)(Bptr + (size_t)k0 * HDIM);

        __syncthreads();
        As[a_k4 + 0][a_row] = av.x;
        As[a_k4 + 1][a_row] = av.y;
        As[a_k4 + 2][a_row] = av.z;
        As[a_k4 + 3][a_row] = av.w;
        *(float4*)&Bs[b_k][b_col] = bv;
        __syncthreads();

#pragma unroll
        for (int k = 0; k < 8; k++) {
            float a[8], b[8];
            *(float4*)(a)     = *(const float4*)&As[k][tr];
            *(float4*)(a + 4) = *(const float4*)&As[k][tr + 4];
            *(float4*)(b)     = *(const float4*)&Bs[k][tc];
            *(float4*)(b + 4) = *(const float4*)&Bs[k][tc + 4];
#pragma unroll
            for (int i = 0; i < 8; i++)
#pragma unroll
                for (int j = 0; j < 8; j++)
                    acc[i][j] = fmaf(a[i], b[j], acc[i][j]);
        }
    }

    float* out = g_xw + (size_t)(bm + tr) * HDIM + bn + tc;
#pragma unroll
    for (int i = 0; i < 8; i++) {
        *(float4*)(out + (size_t)i * HDIM)     = make_float4(acc[i][0], acc[i][1], acc[i][2], acc[i][3]);
        *(float4*)(out + (size_t)i * HDIM + 4) = make_float4(acc[i][4], acc[i][5], acc[i][6], acc[i][7]);
    }
}

// ---------------------------------------------------------------------------
// Kernel B: fused scores + softmax + output per (batch, 64-row tile).
//   S[i,j] = xW[b,i,:] . X[b,j,:] + bias  (j != i), 0 on diagonal
//   P = softmax_row(S);  out[b,i,:] = sum_j P[i,j] X[b,j,:]
// Dynamic smem: S[64][516] + Axw[16][68] + Bt[16][132]
// ---------------------------------------------------------------------------
#define SPAD 516
#define APAD 68
#define BPAD 132
#define SMEM_FLOATS (64 * SPAD + 16 * APAD + 16 * BPAD)

__global__ __launch_bounds__(256) void attn_kernel(const float* __restrict__ X,
                                                   const float* __restrict__ bias_ptr,
                                                   float* __restrict__ out) {
    extern __shared__ float sm[];
    float* S   = sm;                    // 64 x SPAD
    float* Axw = sm + 64 * SPAD;        // 16 x APAD   (k-major xW tile)
    float* Bt  = Axw + 16 * APAD;       // 16 x BPAD   (k-major X tile)

    const int tid = threadIdx.x;
    const int b  = blockIdx.y;
    const int i0 = blockIdx.x * 64;
    const float bias = bias_ptr[0];

    const float* Xb  = X + (size_t)b * NSEQ * HDIM;
    const float* XWb = g_xw + (size_t)(b * NSEQ + i0) * HDIM;

    const int tr = (tid / 16) * 4;    // 0..60  (row microtile)
    const int tc = (tid % 16) * 8;    // 0..120 (col microtile)

    // staging indices (score phase)
    const int ar = tid >> 2;           // 0..63
    const int ak = (tid & 3) * 4;      // 0,4,8,12
    const int bj = tid >> 1;           // 0..127
    const int bk = (tid & 1) * 8;      // 0,8

    // ---------------- score GEMM: S = xW_tile @ Xb^T + bias, diag=0 ----------
    for (int jt = 0; jt < 4; jt++) {
        const int j0 = jt * 128;
        float acc[4][8];
#pragma unroll
        for (int u = 0; u < 4; u++)
#pragma unroll
            for (int v = 0; v < 8; v++) acc[u][v] = 0.0f;

        for (int kk = 0; kk < HDIM; kk += 16) {
            float4 av  = *(const float4*)(XWb + (size_t)ar * HDIM + kk + ak);
            const float* xrow = Xb + (size_t)(j0 + bj) * HDIM + kk + bk;
            float4 bv0 = *(const float4*)(xrow);
            float4 bv1 = *(const float4*)(xrow + 4);

            __syncthreads();
            Axw[(ak + 0) * APAD + ar] = av.x;
            Axw[(ak + 1) * APAD + ar] = av.y;
            Axw[(ak + 2) * APAD + ar] = av.z;
            Axw[(ak + 3) * APAD + ar] = av.w;
            Bt[(bk + 0) * BPAD + bj] = bv0.x;
            Bt[(bk + 1) * BPAD + bj] = bv0.y;
            Bt[(bk + 2) * BPAD + bj] = bv0.z;
            Bt[(bk + 3) * BPAD + bj] = bv0.w;
            Bt[(bk + 4) * BPAD + bj] = bv1.x;
            Bt[(bk + 5) * BPAD + bj] = bv1.y;
            Bt[(bk + 6) * BPAD + bj] = bv1.z;
            Bt[(bk + 7) * BPAD + bj] = bv1.w;
            __syncthreads();

#pragma unroll
            for (int k = 0; k < 16; k++) {
                float a[4], bb[8];
                *(float4*)(a)      = *(const float4*)&Axw[k * APAD + tr];
                *(float4*)(bb)     = *(const float4*)&Bt[k * BPAD + tc];
                *(float4*)(bb + 4) = *(const float4*)&Bt[k * BPAD + tc + 4];
#pragma unroll
                for (int u = 0; u < 4; u++)
#pragma unroll
                    for (int v = 0; v < 8; v++)
                        acc[u][v] = fmaf(a[u], bb[v], acc[u][v]);
            }
        }

        // store scores (bias everywhere except diagonal, which is 0)
#pragma unroll
        for (int u = 0; u < 4; u++)
#pragma unroll
            for (int v = 0; v < 8; v++) {
                const int ig = i0 + tr + u;
                const int jg = j0 + tc + v;
                S[(tr + u) * SPAD + jg] = (ig == jg) ? 0.0f : (acc[u][v] + bias);
            }
    }
    __syncthreads();

    // ---------------- softmax: one warp per row, 8 rows per warp ------------
    const int warp = tid >> 5;
    const int lane = tid & 31;
    for (int rr = 0; rr < 8; rr++) {
        const int row = warp * 8 + rr;
        float* Srow = S + row * SPAD;
        float m = -1e30f;
        for (int j = lane; j < NSEQ; j += 32) m = fmaxf(m, Srow[j]);
#pragma unroll
        for (int o = 16; o > 0; o >>= 1) m = fmaxf(m, __shfl_xor_sync(0xffffffffu, m, o));
        float s = 0.0f;
        for (int j = lane; j < NSEQ; j += 32) {
            float e = __expf(Srow[j] - m);
            Srow[j] = e;
            s += e;
        }
#pragma unroll
        for (int o = 16; o > 0; o >>= 1) s += __shfl_xor_sync(0xffffffffu, s, o);
        const float inv = 1.0f / s;
        for (int j = lane; j < NSEQ; j += 32) Srow[j] *= inv;
    }
    __syncthreads();

    // ---------------- output GEMM: O = P @ Xb  (64 x 768, K = 512) ----------
    const int ok = tid >> 4;           // 0..15 (k-row of staged tile)
    const int oc = (tid & 15) * 8;     // 0..120

    for (int ht = 0; ht < 6; ht++) {
        const int h0 = ht * 128;
        float acc[4][8];
#pragma unroll
        for (int u = 0; u < 4; u++)
#pragma unroll
            for (int v = 0; v < 8; v++) acc[u][v] = 0.0f;

        for (int kk = 0; kk < NSEQ; kk += 16) {
            const float* xrow = Xb + (size_t)(kk + ok) * HDIM + h0 + oc;
            float4 v0 = *(const float4*)(xrow);
            float4 v1 = *(const float4*)(xrow + 4);

            __syncthreads();
            *(float4*)&Bt[ok * BPAD + oc]     = v0;
            *(float4*)&Bt[ok * BPAD + oc + 4] = v1;
            __syncthreads();

#pragma unroll
            for (int k = 0; k < 16; k++) {
                float bb[8];
                *(float4*)(bb)     = *(const float4*)&Bt[k * BPAD + tc];
                *(float4*)(bb + 4) = *(const float4*)&Bt[k * BPAD + tc + 4];
#pragma unroll
                for (int u = 0; u < 4; u++) {
                    const float a = S[(tr + u) * SPAD + kk + k];
#pragma unroll
                    for (int v = 0; v < 8; v++)
                        acc[u][v] = fmaf(a, bb[v], acc[u][v]);
                }
            }
        }

        float* O = out + (size_t)(b * NSEQ + i0 + tr) * HDIM + h0 + tc;
#pragma unroll
        for (int u = 0; u < 4; u++) {
            *(float4*)(O + (size_t)u * HDIM)     = make_float4(acc[u][0], acc[u][1], acc[u][2], acc[u][3]);
            *(float4*)(O + (size_t)u * HDIM + 4) = make_float4(acc[u][4], acc[u][5], acc[u][6], acc[u][7]);
        }
    }
}

// ---------------------------------------------------------------------------
extern "C" void kernel_launch(void* const* d_in, const int* in_sizes, int n_in,
                              void* d_out, int out_size) {
    const float* X    = (const float*)d_in[0];   // [64, 512, 768]
    const float* W    = (const float*)d_in[1];   // [768, 768]
    const float* bptr = (const float*)d_in[2];   // [1]
    float* out = (float*)d_out;                  // [64, 512, 768]

    (void)in_sizes; (void)n_in; (void)out_size;

    const size_t smem_bytes = (size_t)SMEM_FLOATS * sizeof(float);  // ~141.5 KB
    cudaFuncSetAttribute(attn_kernel, cudaFuncAttributeMaxDynamicSharedMemorySize,
                         (int)smem_bytes);

    // Kernel A: xW = X @ W
    dim3 gridA(HDIM / 128, M_TOTAL / 128);   // (6, 256)
    gemm_xw_kernel<<<gridA, 256>>>(X, W);

    // Kernel B: fused scores + softmax + output
    dim3 gridB(NSEQ / 64, BATCH);            // (8, 64)
    attn_kernel<<<gridB, 256, smem_bytes>>>(X, bptr, out);
}

// round 17
// speedup vs baseline: 1.7072x; 1.7055x over previous
#include <cuda_runtime.h>
#include <cuda_bf16.h>
#include <mma.h>
#include <stdint.h>
#include <math.h>

using namespace nvcuda;

#define BATCH 64
#define NSEQ  512
#define HDIM  768
#define M_TOTAL (BATCH * NSEQ)   // 32768

// ---------------------------------------------------------------------------
// Scratch: uint4-backed device globals (16B-aligned bases).
// RULE (root cause of R7-R16 failures): these symbols are ONLY referenced from
// device code. Never passed as kernel arguments from kernel_launch.
// ---------------------------------------------------------------------------
#define ELEMS_X  ((size_t)M_TOTAL * HDIM)          // 25,165,824 bf16
#define ELEMS_W  ((size_t)HDIM * HDIM)             // 589,824 bf16
#define ELEMS_P  ((size_t)BATCH * NSEQ * NSEQ)     // 16,777,216 bf16
__device__ uint4 g_Xhi_ [ELEMS_X / 8];
__device__ uint4 g_Xlo_ [ELEMS_X / 8];
__device__ uint4 g_Whi_ [ELEMS_W / 8];
__device__ uint4 g_Wlo_ [ELEMS_W / 8];
__device__ uint4 g_XWhi_[ELEMS_X / 8];
__device__ uint4 g_XWlo_[ELEMS_X / 8];
__device__ uint4 g_Phi_ [ELEMS_P / 8];
__device__ uint4 g_Plo_ [ELEMS_P / 8];
__device__ uint4 g_S_   [ELEMS_P / 4];             // fp32 raw scores
#define g_Xhi  ((__nv_bfloat16*)g_Xhi_)
#define g_Xlo  ((__nv_bfloat16*)g_Xlo_)
#define g_Whi  ((__nv_bfloat16*)g_Whi_)
#define g_Wlo  ((__nv_bfloat16*)g_Wlo_)
#define g_XWhi ((__nv_bfloat16*)g_XWhi_)
#define g_XWlo ((__nv_bfloat16*)g_XWlo_)
#define g_Phi  ((__nv_bfloat16*)g_Phi_)
#define g_Plo  ((__nv_bfloat16*)g_Plo_)
#define g_S    ((float*)g_S_)

__device__ __forceinline__ void split2(float v, __nv_bfloat16& h, __nv_bfloat16& l) {
    h = __float2bfloat16(v);
    l = __float2bfloat16(v - __bfloat162float(h));
}

// ---------------------------------------------------------------------------
// Prep: split fp32 -> bf16 hi/lo. Destinations are device globals referenced
// from device code (NOT kernel arguments).
// ---------------------------------------------------------------------------
__device__ __forceinline__ void split_body(const float* __restrict__ src,
                                           __nv_bfloat16* dh, __nv_bfloat16* dl, int n4) {
    int i = blockIdx.x * 256 + threadIdx.x;
    if (i >= n4) return;
    float4 v = ((const float4*)src)[i];
    __nv_bfloat16 h0,l0,h1,l1,h2,l2,h3,l3;
    split2(v.x, h0, l0); split2(v.y, h1, l1);
    split2(v.z, h2, l2); split2(v.w, h3, l3);
    __nv_bfloat162 a; a.x=h0; a.y=h1; __nv_bfloat162 b; b.x=h2; b.y=h3;
    __nv_bfloat162 c; c.x=l0; c.y=l1; __nv_bfloat162 d; d.x=l2; d.y=l3;
    *(__nv_bfloat162*)(dh + 4*i)     = a;
    *(__nv_bfloat162*)(dh + 4*i + 2) = b;
    *(__nv_bfloat162*)(dl + 4*i)     = c;
    *(__nv_bfloat162*)(dl + 4*i + 2) = d;
}

__global__ __launch_bounds__(256) void split_x_kernel(const float* __restrict__ src) {
    split_body(src, g_Xhi, g_Xlo, (int)(ELEMS_X / 4));
}
__global__ __launch_bounds__(256) void split_w_kernel(const float* __restrict__ src) {
    split_body(src, g_Whi, g_Wlo, (int)(ELEMS_W / 4));
}

// ---------------------------------------------------------------------------
// wmma mainloop: CTA tile 128(m) x 128(n), k-chunk 64, single-buffered smem,
// plain synchronous staging.
// A: 128 rows x K, row-major (k contiguous), stride lda.
// B (BCOL=false): row-major [k][n], stride ldb; base pre-offset by n0.
// B (BCOL=true) : [n][k] rows (k contiguous); col-major fragments.
// K walked over 3 split segments (hi*hi + lo*hi + hi*lo) of KSEG chunks.
// 8 warps = 4(m) x 2(n); warp tile 32 x 64 = 2 x 4 fragments of 16x16.
// ---------------------------------------------------------------------------
#define LDA_S   72                    // padded A/Bcol row stride (elems)
#define LDB_ROW 136                   // padded Brow row stride (elems)
#define A_ELEMS (128 * LDA_S)         // 9216

typedef wmma::fragment<wmma::accumulator, 16, 16, 16, float> AccFrag;

template <int KSEG, bool BCOL>
__device__ __forceinline__ void wmma_loop(
    const __nv_bfloat16* A0, const __nv_bfloat16* A1, const __nv_bfloat16* A2, int lda,
    const __nv_bfloat16* B0, const __nv_bfloat16* B1, const __nv_bfloat16* B2, int ldb,
    __nv_bfloat16* sm, AccFrag (&acc)[2][4])
{
    const int tid = threadIdx.x;
    const int wid = tid >> 5;
    const int wm  = wid & 3;      // 0..3 (m)
    const int wn  = wid >> 2;     // 0..1 (n)
    __nv_bfloat16* Asm = sm;
    __nv_bfloat16* Bsm = sm + A_ELEMS;

#pragma unroll
    for (int i = 0; i < 2; i++)
#pragma unroll
        for (int j = 0; j < 4; j++) wmma::fill_fragment(acc[i][j], 0.0f);

    const __nv_bfloat16* As[3] = {A0, A1, A2};
    const __nv_bfloat16* Bs[3] = {B0, B1, B2};

    for (int t = 0; t < 3 * KSEG; t++) {
        const int seg = t / KSEG;
        const int k0  = (t % KSEG) * 64;
        const __nv_bfloat16* Ap = As[seg];
        const __nv_bfloat16* Bp = Bs[seg];

        __syncthreads();   // previous chunk's compute done before overwrite
#pragma unroll
        for (int it = 0; it < 4; it++) {
            const int idx = tid + it * 256;
            {   // A: 128 rows x 64 cols = 1024 uint4
                const int r = idx >> 3, c = idx & 7;
                *(uint4*)(Asm + r * LDA_S + c * 8) =
                    *(const uint4*)(Ap + (size_t)r * lda + k0 + c * 8);
            }
            if (BCOL) {   // B: 128 n-rows x 64 k
                const int r = idx >> 3, c = idx & 7;
                *(uint4*)(Bsm + r * LDA_S + c * 8) =
                    *(const uint4*)(Bp + (size_t)r * ldb + k0 + c * 8);
            } else {      // B row-major: 64 k-rows x 128 n
                const int r = idx >> 4, c = idx & 15;
                *(uint4*)(Bsm + r * LDB_ROW + c * 8) =
                    *(const uint4*)(Bp + (size_t)(k0 + r) * ldb + c * 8);
            }
        }
        __syncthreads();

#pragma unroll
        for (int kk = 0; kk < 4; kk++) {
            wmma::fragment<wmma::matrix_a, 16, 16, 16, __nv_bfloat16, wmma::row_major> af[2];
#pragma unroll
            for (int i = 0; i < 2; i++)
                wmma::load_matrix_sync(af[i], Asm + (wm * 32 + i * 16) * LDA_S + kk * 16, LDA_S);

            if (BCOL) {
                wmma::fragment<wmma::matrix_b, 16, 16, 16, __nv_bfloat16, wmma::col_major> bf[4];
#pragma unroll
                for (int j = 0; j < 4; j++)
                    wmma::load_matrix_sync(bf[j], Bsm + (wn * 64 + j * 16) * LDA_S + kk * 16, LDA_S);
#pragma unroll
                for (int i = 0; i < 2; i++)
#pragma unroll
                    for (int j = 0; j < 4; j++)
                        wmma::mma_sync(acc[i][j], af[i], bf[j], acc[i][j]);
            } else {
                wmma::fragment<wmma::matrix_b, 16, 16, 16, __nv_bfloat16, wmma::row_major> bf[4];
#pragma unroll
                for (int j = 0; j < 4; j++)
                    wmma::load_matrix_sync(bf[j], Bsm + (kk * 16) * LDB_ROW + wn * 64 + j * 16, LDB_ROW);
#pragma unroll
                for (int i = 0; i < 2; i++)
#pragma unroll
                    for (int j = 0; j < 4; j++)
                        wmma::mma_sync(acc[i][j], af[i], bf[j], acc[i][j]);
            }
        }
    }
}

// ---------------------------------------------------------------------------
// GEMM1: XW = X @ W. B = W row-major over h. Split epilogue via smem.
// ---------------------------------------------------------------------------
#define LDC_S 132
#define SMEM_G1 (128 * LDC_S * 4)     // 67584 (>= staging 35840)

__global__ __launch_bounds__(256) void gemm1_kernel() {
    extern __shared__ __align__(16) char smraw[];
    __nv_bfloat16* sm = (__nv_bfloat16*)smraw;
    const int bn0 = blockIdx.x * 128;
    const int bm0 = blockIdx.y * 128;

    AccFrag acc[2][4];
    wmma_loop<12, false>(g_Xhi + (size_t)bm0 * HDIM, g_Xlo + (size_t)bm0 * HDIM,
                         g_Xhi + (size_t)bm0 * HDIM, HDIM,
                         g_Whi + bn0, g_Whi + bn0, g_Wlo + bn0, HDIM,
                         sm, acc);

    float* Csm = (float*)smraw;
    const int wid = threadIdx.x >> 5, wm = wid & 3, wn = wid >> 2;
    __syncthreads();
#pragma unroll
    for (int i = 0; i < 2; i++)
#pragma unroll
        for (int j = 0; j < 4; j++)
            wmma::store_matrix_sync(Csm + (wm * 32 + i * 16) * LDC_S + wn * 64 + j * 16,
                                    acc[i][j], LDC_S, wmma::mem_row_major);
    __syncthreads();

    const int row = threadIdx.x >> 1;
    const int cb  = (threadIdx.x & 1) * 64;
    __nv_bfloat16* ph = g_XWhi + (size_t)(bm0 + row) * HDIM + bn0 + cb;
    __nv_bfloat16* pl = g_XWlo + (size_t)(bm0 + row) * HDIM + bn0 + cb;
#pragma unroll
    for (int j = 0; j < 64; j += 2) {
        __nv_bfloat16 h0, l0, h1, l1;
        split2(Csm[row * LDC_S + cb + j],     h0, l0);
        split2(Csm[row * LDC_S + cb + j + 1], h1, l1);
        __nv_bfloat162 vh; vh.x = h0; vh.y = h1;
        __nv_bfloat162 vl; vl.x = l0; vl.y = l1;
        *(__nv_bfloat162*)(ph + j) = vh;
        *(__nv_bfloat162*)(pl + j) = vl;
    }
}

// ---------------------------------------------------------------------------
// GEMM2: S = XW @ X^T. B = X rows as col-major (n = j, k = h). fp32 store.
// ---------------------------------------------------------------------------
#define SMEM_G2 (2 * A_ELEMS * 2)     // 36864

__global__ __launch_bounds__(256) void gemm2_kernel() {
    extern __shared__ __align__(16) char smraw[];
    __nv_bfloat16* sm = (__nv_bfloat16*)smraw;
    const int bn0 = blockIdx.x * 128;
    const int bm0 = blockIdx.y * 128;
    const int b   = blockIdx.z;
    const __nv_bfloat16* Ah = g_XWhi + ((size_t)b * NSEQ + bm0) * HDIM;
    const __nv_bfloat16* Al = g_XWlo + ((size_t)b * NSEQ + bm0) * HDIM;
    const __nv_bfloat16* Bh = g_Xhi  + ((size_t)b * NSEQ + bn0) * HDIM;
    const __nv_bfloat16* Bl = g_Xlo  + ((size_t)b * NSEQ + bn0) * HDIM;

    AccFrag acc[2][4];
    wmma_loop<12, true>(Ah, Al, Ah, HDIM, Bh, Bh, Bl, HDIM, sm, acc);

    const int wid = threadIdx.x >> 5, wm = wid & 3, wn = wid >> 2;
    float* Sb = g_S + (size_t)b * NSEQ * NSEQ + (size_t)bm0 * NSEQ + bn0;
#pragma unroll
    for (int i = 0; i < 2; i++)
#pragma unroll
        for (int j = 0; j < 4; j++)
            wmma::store_matrix_sync(Sb + (size_t)(wm * 32 + i * 16) * NSEQ + wn * 64 + j * 16,
                                    acc[i][j], NSEQ, wmma::mem_row_major);
}

// ---------------------------------------------------------------------------
// Softmax: bias + zero-diag + row softmax + split P to bf16 hi/lo.
// ---------------------------------------------------------------------------
__global__ __launch_bounds__(256) void softmax_kernel(const float* __restrict__ bias_ptr) {
    const int b = blockIdx.y;
    const int warp = threadIdx.x >> 5, lane = threadIdx.x & 31;
    const int i = blockIdx.x * 8 + warp;
    const float bias = bias_ptr[0];
    const float* Srow = g_S + ((size_t)b * NSEQ + i) * NSEQ;

    float v[16];
    float mx = -1e30f;
#pragma unroll
    for (int k = 0; k < 16; k++) {
        const int j = k * 32 + lane;
        float x = Srow[j] + bias;
        if (j == i) x = 0.0f;
        v[k] = x;
        mx = fmaxf(mx, x);
    }
#pragma unroll
    for (int o = 16; o > 0; o >>= 1) mx = fmaxf(mx, __shfl_xor_sync(0xffffffffu, mx, o));
    float s = 0.0f;
#pragma unroll
    for (int k = 0; k < 16; k++) {
        v[k] = __expf(v[k] - mx);
        s += v[k];
    }
#pragma unroll
    for (int o = 16; o > 0; o >>= 1) s += __shfl_xor_sync(0xffffffffu, s, o);
    const float inv = 1.0f / s;

    __nv_bfloat16* Ph = g_Phi + ((size_t)b * NSEQ + i) * NSEQ;
    __nv_bfloat16* Pl = g_Plo + ((size_t)b * NSEQ + i) * NSEQ;
#pragma unroll
    for (int k = 0; k < 16; k++) {
        const int j = k * 32 + lane;
        __nv_bfloat16 h, l;
        split2(v[k] * inv, h, l);
        Ph[j] = h; Pl[j] = l;
    }
}

// ---------------------------------------------------------------------------
// GEMM3: out = P @ X. B = X row-major over j. fp32 direct store.
// ---------------------------------------------------------------------------
#define SMEM_G3 (A_ELEMS * 2 + 64 * LDB_ROW * 2)   // 35840

__global__ __launch_bounds__(256) void gemm3_kernel(float* __restrict__ out) {
    extern __shared__ __align__(16) char smraw[];
    __nv_bfloat16* sm = (__nv_bfloat16*)smraw;
    const int bn0 = blockIdx.x * 128;
    const int bm0 = blockIdx.y * 128;
    const int b   = blockIdx.z;
    const __nv_bfloat16* Ah = g_Phi + ((size_t)b * NSEQ + bm0) * NSEQ;
    const __nv_bfloat16* Al = g_Plo + ((size_t)b * NSEQ + bm0) * NSEQ;
    const __nv_bfloat16* Bh = g_Xhi + (size_t)b * NSEQ * HDIM + bn0;
    const __nv_bfloat16* Bl = g_Xlo + (size_t)b * NSEQ * HDIM + bn0;

    AccFrag acc[2][4];
    wmma_loop<8, false>(Ah, Al, Ah, NSEQ, Bh, Bh, Bl, HDIM, sm, acc);

    const int wid = threadIdx.x >> 5, wm = wid & 3, wn = wid >> 2;
    float* Ob = out + (size_t)b * NSEQ * HDIM + (size_t)bm0 * HDIM + bn0;
#pragma unroll
    for (int i = 0; i < 2; i++)
#pragma unroll
        for (int j = 0; j < 4; j++)
            wmma::store_matrix_sync(Ob + (size_t)(wm * 32 + i * 16) * HDIM + wn * 64 + j * 16,
                                    acc[i][j], HDIM, wmma::mem_row_major);
}

// ---------------------------------------------------------------------------
extern "C" void kernel_launch(void* const* d_in, const int* in_sizes, int n_in,
                              void* d_out, int out_size) {
    const float* X    = (const float*)d_in[0];   // [64, 512, 768]
    const float* W    = (const float*)d_in[1];   // [768, 768]
    const float* bptr = (const float*)d_in[2];   // [1]
    float* out = (float*)d_out;                  // [64, 512, 768]
    (void)in_sizes; (void)n_in; (void)out_size;

    cudaFuncSetAttribute(gemm1_kernel, cudaFuncAttributeMaxDynamicSharedMemorySize, SMEM_G1);
    cudaFuncSetAttribute(gemm2_kernel, cudaFuncAttributeMaxDynamicSharedMemorySize, SMEM_G2);
    cudaFuncSetAttribute(gemm3_kernel, cudaFuncAttributeMaxDynamicSharedMemorySize, SMEM_G3);

    // Prep: split X and W to bf16 hi/lo. Outputs are device globals written
    // from device code — no __device__ symbol is passed as a kernel argument.
    const int nx4 = (int)(ELEMS_X / 4);
    split_x_kernel<<<(nx4 + 255) / 256, 256>>>(X);
    const int nw4 = (int)(ELEMS_W / 4);
    split_w_kernel<<<(nw4 + 255) / 256, 256>>>(W);

    // GEMM1: XW = X @ W
    gemm1_kernel<<<dim3(HDIM / 128, M_TOTAL / 128), 256, SMEM_G1>>>();
    // GEMM2: raw scores S = XW @ X^T
    gemm2_kernel<<<dim3(NSEQ / 128, NSEQ / 128, BATCH), 256, SMEM_G2>>>();
    // Softmax + P split
    softmax_kernel<<<dim3(NSEQ / 8, BATCH), 256>>>(bptr);
    // GEMM3: out = P @ X
    gemm3_kernel<<<dim3(HDIM / 128, NSEQ / 128, BATCH), 256, SMEM_G3>>>(out);
}